// round 10
// baseline (speedup 1.0000x reference)
#include <cuda_runtime.h>

// qkv scratch in windowed layout: [b(2)][wy(16)][wx(16)][ch(56)][Bs(8)][tok(64)]
#define NELEM_QKV (2*16*16*56*8*64)
__device__ float g_q[NELEM_QKV];
__device__ float g_k[NELEM_QKV];
__device__ float g_v[NELEM_QKV];
// sigma scratch: [win*4+head][Bs][64] (Sk stored PERMUTED), theta: [sbid*8+Bs]
__device__ float g_sq[2048 * 512];
__device__ float g_sk[2048 * 512];
__device__ float g_theta[16384];

// ---------------------------------------------------------------------------
// Grouped 3x3x3 convs for ONE (batch, wy-quarter) chunk. Halo via shuffle.
// z<56: q from x (o=z). z>=56: k/v from last interleaved (L2 reuse).
// grid (1, 4, 168): blockIdx.y covers 4 wy values (32 h rows) of the quarter.
// ---------------------------------------------------------------------------
__global__ __launch_bounds__(256) void conv_all_kernel(
    const float* __restrict__ x, const float* __restrict__ last,
    const float* __restrict__ Wq, const float* __restrict__ Wk,
    const float* __restrict__ Wv, int b, int quarter)
{
  const int z = blockIdx.z;
  int o, sel;
  if (z < 56) { o = z; sel = 0; }
  else { int t = z - 56; o = t >> 1; sel = 1 + (t & 1); }
  const float* in = (sel == 0) ? x : last;
  const float* W3 = (sel == 0) ? Wq : (sel == 1) ? Wk : Wv;
  float* outw     = (sel == 0) ? g_q : (sel == 1) ? g_k : g_v;

  const int h = (quarter * 4 + blockIdx.y) * 8 + threadIdx.y;
  const int tx = threadIdx.x;
  const int w0 = tx * 4;

  __shared__ float ws[54];
  const int tid = threadIdx.y * 32 + tx;
  if (tid < 54) ws[tid] = W3[o * 54 + tid];
  __syncthreads();

  float acc[8][4];
#pragma unroll
  for (int i = 0; i < 8; i++) {
    acc[i][0] = 0.f; acc[i][1] = 0.f; acc[i][2] = 0.f; acc[i][3] = 0.f;
  }

#pragma unroll
  for (int ci = 0; ci < 2; ci++) {
    const float* basec = in + (size_t)((b * 112 + o * 2 + ci) * 8) * 16384;
#pragma unroll
    for (int dh = 0; dh < 3; dh++) {
      const int hh = h + dh - 1;
      if (hh < 0 || hh > 127) continue;
      float w9[3][3];
#pragma unroll
      for (int kd = 0; kd < 3; kd++)
#pragma unroll
        for (int dw = 0; dw < 3; dw++)
          w9[kd][dw] = ws[ci * 27 + kd * 9 + dh * 3 + dw];
      const float* rowp = basec + hh * 128 + w0;
#pragma unroll
      for (int d = 0; d < 8; d++) {
        const float* p = rowp + d * 16384;
        float4 m4 = *(const float4*)p;
        float vl = __shfl_up_sync(0xffffffffu, m4.w, 1);
        float vr = __shfl_down_sync(0xffffffffu, m4.x, 1);
        float v[6];
        v[0] = (tx == 0)  ? 0.f : vl;
        v[1] = m4.x; v[2] = m4.y; v[3] = m4.z; v[4] = m4.w;
        v[5] = (tx == 31) ? 0.f : vr;
#pragma unroll
        for (int kd = 0; kd < 3; kd++) {
          const int Bs = d + 1 - kd;
          if (Bs < 0 || Bs > 7) continue;
#pragma unroll
          for (int dw = 0; dw < 3; dw++) {
            const float wv = w9[kd][dw];
            acc[Bs][0] += wv * v[dw + 0];
            acc[Bs][1] += wv * v[dw + 1];
            acc[Bs][2] += wv * v[dw + 2];
            acc[Bs][3] += wv * v[dw + 3];
          }
        }
      }
    }
  }

  const int wy = h >> 3, ty = h & 7, wx = w0 >> 3, tx0 = w0 & 7;
  float* op = outw + (size_t)((((b * 16 + wy) * 16 + wx) * 56 + o) * 8) * 64
                   + ty * 8 + tx0;
#pragma unroll
  for (int Bs = 0; Bs < 8; Bs++) {
    *(float4*)(op + Bs * 64) =
        make_float4(acc[Bs][0], acc[Bs][1], acc[Bs][2], acc[Bs][3]);
  }
}

// ---------------------------------------------------------------------------
// Sigma kernel (per chunk): Sq, Sk (permuted), theta for all 8 slices.
// t1_i = q_i.Kbar - m1_i*(q_i.k_i).  bid = bid_base + blockIdx.x.
// ---------------------------------------------------------------------------
__global__ __launch_bounds__(256) void sigma_kernel(
    const float* __restrict__ pcq_w, const float* __restrict__ pcq_b,
    const float* __restrict__ pck_w, const float* __restrict__ pck_b,
    const float* __restrict__ mlp1_w, const float* __restrict__ mlp2_w1,
    const float* __restrict__ mlp2_w2, int bid_base)
{
  __shared__ __align__(16) float m1[64], w2[64];
  __shared__ __align__(16) float kbar_s[128];    // [Bs][16]
  __shared__ __align__(16) float t1_all[512];    // [Bs][64]
  __shared__ __align__(16) float red2[512];
  __shared__ float pcqw[14], pckw[14];

  const int tid = threadIdx.x;
  const int bid = bid_base + blockIdx.x;    // win*4 + head
  const int head = bid & 3, win = bid >> 2;
  const int b = win >> 8, wy = (win >> 4) & 15, wx = win & 15;

  if (tid < 64) { m1[tid] = mlp1_w[tid]; w2[tid] = mlp2_w2[tid]; }
  if (tid < 14) { pcqw[tid] = pcq_w[tid]; pckw[tid] = pck_w[tid]; }
  const float bq = pcq_b[0], bk = pck_b[0];

  const size_t wbase = (size_t)((b * 16 + wy) * 16 + wx) * (56 * 8 * 64);
  const float* gqf = g_q + wbase + head * 14 * 512;
  const float* gkf = g_k + wbase + head * 14 * 512;
  const float4* gk = (const float4*)gkf;
  const float4* m14 = (const float4*)m1;
  const float4* t14 = (const float4*)t1_all;
  const float4* w14 = (const float4*)mlp2_w1;
  __syncthreads();

  // P1: Kbar[Bs][d]
#pragma unroll
  for (int rep = 0; rep < 2; rep++) {
    const int item = rep * 64 + (tid >> 2);
    const int p4 = tid & 3;
    if (item < 112) {
      const int Bs = item / 14, d = item % 14;
      float pr = 0.f;
#pragma unroll
      for (int c = 0; c < 4; c++) {
        float4 kv = gk[d * 128 + Bs * 16 + p4 * 4 + c];
        float4 mm = m14[p4 * 4 + c];
        pr += kv.x*mm.x + kv.y*mm.y + kv.z*mm.z + kv.w*mm.w;
      }
      pr += __shfl_xor_sync(0xffffffffu, pr, 1);
      pr += __shfl_xor_sync(0xffffffffu, pr, 2);
      if (p4 == 0) kbar_s[Bs * 16 + d] = pr;
    }
  }
  __syncthreads();

  // P2: per (Bs,i): Sq, Sk (permuted), t1
#pragma unroll
  for (int rep = 0; rep < 2; rep++) {
    const int t = tid + rep * 256;
    const int Bs = t >> 6, i = t & 63;
    float sq = bq, sk = bk, qkb = 0.f, dg = 0.f;
#pragma unroll
    for (int d = 0; d < 14; d++) {
      float qv = gqf[d * 512 + Bs * 64 + i];
      float kv = gkf[d * 512 + Bs * 64 + i];
      sq  += qv * pcqw[d];
      sk  += kv * pckw[d];
      qkb += qv * kbar_s[Bs * 16 + d];
      dg  += qv * kv;
    }
    g_sq[(size_t)bid * 512 + Bs * 64 + i] = sq;
    g_sk[(size_t)bid * 512 + Bs * 64 +
         ((((i >> 2) & 3) * 4 + (i >> 4)) * 4 + (i & 3))] = sk;
    t1_all[Bs * 64 + i] = qkb - m1[i] * dg;
  }
  __syncthreads();

  // P3: t2 = leaky(t1 @ w1^T); red2 = t2 * w2
#pragma unroll
  for (int rep = 0; rep < 2; rep++) {
    const int t = tid + rep * 256;
    const int Bs = t >> 6, o = t & 63;
    float s = 0.f;
#pragma unroll
    for (int c = 0; c < 16; c++) {
      float4 wv = __ldg(&w14[o * 16 + c]);
      float4 tv = t14[Bs * 16 + c];
      s += wv.x*tv.x + wv.y*tv.y + wv.z*tv.z + wv.w*tv.w;
    }
    s = (s > 0.f) ? s : 0.1f * s;
    red2[Bs * 64 + o] = s * w2[o];
  }
  __syncthreads();

  // P4: theta[Bs]
  {
    const int w = tid >> 5, lane = tid & 31;
    float s = red2[w * 64 + lane] + red2[w * 64 + lane + 32];
#pragma unroll
    for (int off = 16; off > 0; off >>= 1)
      s += __shfl_xor_sync(0xffffffffu, s, off);
    if (lane == 0) g_theta[bid * 8 + w] = s;
  }
}

// ---------------------------------------------------------------------------
// Slice attention: one block per (win, head, Bs). bid = bid_base + blockIdx.x.
// ---------------------------------------------------------------------------
__global__ __launch_bounds__(256, 4) void attn_slice_kernel(
    const float* __restrict__ Wout, float* __restrict__ out, int bid_base)
{
  __shared__ __align__(16) float q_s[896], k_s[896], v_s[896];
  __shared__ __align__(16) float sim[64 * 68];
  __shared__ __align__(16) float sks[64];
  __shared__ float woutc[28];
  __shared__ float theta_sh;

  const int tid = threadIdx.x;
  const int bid = bid_base + blockIdx.x;    // win*32 + head*8 + Bs
  const int Bs = bid & 7, head = (bid >> 3) & 3, win = bid >> 5;
  const int b = win >> 8, wy = (win >> 4) & 15, wx = win & 15;
  const int sidx = (bid >> 3) * 512 + Bs * 64;

  const size_t wbase = (size_t)((b * 16 + wy) * 16 + wx) * (56 * 8 * 64);
  const float4* gq = (const float4*)(g_q + wbase + head * 14 * 512);
  const float4* gk = (const float4*)(g_k + wbase + head * 14 * 512);
  const float4* gv = (const float4*)(g_v + wbase + head * 14 * 512);

  float4* q4 = (float4*)q_s; float4* k4 = (float4*)k_s; float4* v4 = (float4*)v_s;
  float4* sim4 = (float4*)sim;
  const float4* Sks4 = (const float4*)sks;

  const int irow = tid >> 2, p4 = tid & 3;
  const int it = tid >> 4, jt = tid & 15;
  const int hh = wy * 8 + (irow >> 3), ww = wx * 8 + (irow & 7);

  if (tid < 224) {
    int d = tid >> 4, t4 = tid & 15;
    int ga = d * 128 + Bs * 16 + t4;
    q4[d * 16 + t4] = gq[ga];
    k4[d * 16 + t4] = gk[ga];
    v4[d * 16 + (t4 & 3) * 4 + (t4 >> 2)] = gv[ga];
  } else {
    int t = tid - 224;
    if (t < 16) ((float4*)sks)[t] = ((const float4*)(g_sk + sidx))[t];
    if (t < 28) woutc[t] = Wout[head * 28 + t];
    if (t == 28) theta_sh = g_theta[bid];
  }
  __syncthreads();

  // sim = q^T k (4x4 register-tiled GEMM)
  {
    float a00=0,a01=0,a02=0,a03=0, a10=0,a11=0,a12=0,a13=0;
    float a20=0,a21=0,a22=0,a23=0, a30=0,a31=0,a32=0,a33=0;
#pragma unroll
    for (int d = 0; d < 14; d++) {
      float4 qv = q4[d * 16 + it];
      float4 kv = k4[d * 16 + jt];
      a00 += qv.x*kv.x; a01 += qv.x*kv.y; a02 += qv.x*kv.z; a03 += qv.x*kv.w;
      a10 += qv.y*kv.x; a11 += qv.y*kv.y; a12 += qv.y*kv.z; a13 += qv.y*kv.w;
      a20 += qv.z*kv.x; a21 += qv.z*kv.y; a22 += qv.z*kv.z; a23 += qv.z*kv.w;
      a30 += qv.w*kv.x; a31 += qv.w*kv.y; a32 += qv.w*kv.z; a33 += qv.w*kv.w;
    }
    const int rbase = it * 4;
    sim4[(rbase+0) * 17 + jt] = make_float4(a00,a01,a02,a03);
    sim4[(rbase+1) * 17 + jt] = make_float4(a10,a11,a12,a13);
    sim4[(rbase+2) * 17 + jt] = make_float4(a20,a21,a22,a23);
    sim4[(rbase+3) * 17 + jt] = make_float4(a30,a31,a32,a33);
  }
  __syncthreads();

  // scale, softmax, mask, out-GEMM, store
  {
    const float sq = g_sq[sidx + irow];
    const float th = theta_sh;
    float a[16];
    float m = -1e30f;
#pragma unroll
    for (int c = 0; c < 4; c++) {
      float4 sv = sim4[irow * 17 + p4 * 4 + c];
      float4 kv = Sks4[c * 4 + p4];
      a[c*4+0] = sv.x * sq * kv.x; a[c*4+1] = sv.y * sq * kv.y;
      a[c*4+2] = sv.z * sq * kv.z; a[c*4+3] = sv.w * sq * kv.w;
      m = fmaxf(m, fmaxf(fmaxf(a[c*4+0], a[c*4+1]), fmaxf(a[c*4+2], a[c*4+3])));
    }
    m = fmaxf(m, __shfl_xor_sync(0xffffffffu, m, 1));
    m = fmaxf(m, __shfl_xor_sync(0xffffffffu, m, 2));
    float sum = 0.f;
#pragma unroll
    for (int e = 0; e < 16; e++) {
      float xv = a[e];
      float ev = __expf(xv - m);
      sum += ev;
      a[e] = (xv > th) ? ev : 0.f;
    }
    sum += __shfl_xor_sync(0xffffffffu, sum, 1);
    sum += __shfl_xor_sync(0xffffffffu, sum, 2);
    const float r = 1.f / sum;
#pragma unroll
    for (int e = 0; e < 16; e++) a[e] *= r;

    const size_t sp = (size_t)Bs * 16384 + hh * 128 + ww;
    const size_t cb = (size_t)(b * 112 + head * 28) * 131072 + sp;
#pragma unroll
    for (int half = 0; half < 2; half++) {
      float oacc[7] = {0.f,0.f,0.f,0.f,0.f,0.f,0.f};
#pragma unroll
      for (int dd = 0; dd < 7; dd++) {
        const int d = half * 7 + dd;
#pragma unroll
        for (int c = 0; c < 4; c++) {
          float4 vv = v4[d * 16 + c * 4 + p4];
          oacc[dd] += a[c*4+0]*vv.x + a[c*4+1]*vv.y
                    + a[c*4+2]*vv.z + a[c*4+3]*vv.w;
        }
      }
#pragma unroll
      for (int dd = 0; dd < 7; dd++) {
        float s = oacc[dd];
        s += __shfl_xor_sync(0xffffffffu, s, 1);
        s += __shfl_xor_sync(0xffffffffu, s, 2);
        oacc[dd] = s;
      }
#pragma unroll
      for (int k = 0; k < 2; k++) {
        const int dd = p4 + 4 * k;
        if (dd < 7) {
          const int d = half * 7 + dd;
          out[cb + (size_t)(2 * d)     * 131072] = oacc[dd] * woutc[d * 2 + 0];
          out[cb + (size_t)(2 * d + 1) * 131072] = oacc[dd] * woutc[d * 2 + 1];
        }
      }
    }
  }
}

extern "C" void kernel_launch(void* const* d_in, const int* in_sizes, int n_in,
                              void* d_out, int out_size) {
  (void)in_sizes; (void)n_in; (void)out_size;
  const float* x      = (const float*)d_in[0];
  const float* last   = (const float*)d_in[1];
  const float* Wq     = (const float*)d_in[2];
  const float* Wk     = (const float*)d_in[3];
  const float* Wv     = (const float*)d_in[4];
  const float* Wout   = (const float*)d_in[5];
  const float* pcq_w  = (const float*)d_in[6];
  const float* pcq_b  = (const float*)d_in[7];
  const float* pck_w  = (const float*)d_in[8];
  const float* pck_b  = (const float*)d_in[9];
  const float* mlp1_w = (const float*)d_in[10];
  const float* mlp2w1 = (const float*)d_in[11];
  const float* mlp2w2 = (const float*)d_in[12];
  float* out = (float*)d_out;

  // lazily-created streams/events (resource init only; work is identical
  // every call and fully event-ordered -> deterministic, graph-capturable)
  static cudaStream_t s1 = 0, s2 = 0;
  static cudaEvent_t evF = 0, evC[8], evJ1 = 0, evJ2 = 0;
  if (s1 == 0) {
    cudaStreamCreateWithFlags(&s1, cudaStreamNonBlocking);
    cudaStreamCreateWithFlags(&s2, cudaStreamNonBlocking);
    cudaEventCreateWithFlags(&evF, cudaEventDisableTiming);
    for (int i = 0; i < 8; i++)
      cudaEventCreateWithFlags(&evC[i], cudaEventDisableTiming);
    cudaEventCreateWithFlags(&evJ1, cudaEventDisableTiming);
    cudaEventCreateWithFlags(&evJ2, cudaEventDisableTiming);
  }

  // fork from the caller's (captured) stream
  cudaEventRecord(evF, 0);
  cudaStreamWaitEvent(s1, evF, 0);
  cudaStreamWaitEvent(s2, evF, 0);

  // conv chunks on s1
  for (int c = 0; c < 8; c++) {
    const int b = c >> 2, qtr = c & 3;
    conv_all_kernel<<<dim3(1, 4, 168), dim3(32, 8), 0, s1>>>(
        x, last, Wq, Wk, Wv, b, qtr);
    cudaEventRecord(evC[c], s1);
  }
  // sigma + attn chunks on s2, each gated only on its conv chunk
  for (int c = 0; c < 8; c++) {
    const int b = c >> 2, qtr = c & 3;
    const int wb = b * 256 + qtr * 64;
    cudaStreamWaitEvent(s2, evC[c], 0);
    sigma_kernel<<<256, 256, 0, s2>>>(pcq_w, pcq_b, pck_w, pck_b,
                                      mlp1_w, mlp2w1, mlp2w2, wb * 4);
    attn_slice_kernel<<<2048, 256, 0, s2>>>(Wout, out, wb * 32);
  }

  // join back to the caller's stream
  cudaEventRecord(evJ1, s1);
  cudaEventRecord(evJ2, s2);
  cudaStreamWaitEvent(0, evJ1, 0);
  cudaStreamWaitEvent(0, evJ2, 0);
}

// round 11
// speedup vs baseline: 1.0832x; 1.0832x over previous
#include <cuda_runtime.h>

// qkv scratch in windowed layout: [b(2)][wy(16)][wx(16)][ch(56)][Bs(8)][tok(64)]
#define NELEM_QKV (2*16*16*56*8*64)
__device__ float g_q[NELEM_QKV];
__device__ float g_k[NELEM_QKV];
__device__ float g_v[NELEM_QKV];
// sigma scratch: [win*4+head][Bs][64] (Sk stored PERMUTED), theta: [sbid*8+Bs]
__device__ float g_sq[2048 * 512];
__device__ float g_sk[2048 * 512];
__device__ float g_theta[16384];

// ---------------------------------------------------------------------------
// Grouped 3x3x3 convs for ONE batch. Halo via warp shuffle.
// z<56: q from x (o=z). z>=56: k/v from last interleaved (L2 reuse).
// grid (1, 16, 168), block (32, 8)  -> 2688 blocks (full-chip efficiency).
// ---------------------------------------------------------------------------
__global__ __launch_bounds__(256) void conv_all_kernel(
    const float* __restrict__ x, const float* __restrict__ last,
    const float* __restrict__ Wq, const float* __restrict__ Wk,
    const float* __restrict__ Wv, int b)
{
  const int z = blockIdx.z;
  int o, sel;
  if (z < 56) { o = z; sel = 0; }
  else { int t = z - 56; o = t >> 1; sel = 1 + (t & 1); }
  const float* in = (sel == 0) ? x : last;
  const float* W3 = (sel == 0) ? Wq : (sel == 1) ? Wk : Wv;
  float* outw     = (sel == 0) ? g_q : (sel == 1) ? g_k : g_v;

  const int h = blockIdx.y * 8 + threadIdx.y;
  const int tx = threadIdx.x;
  const int w0 = tx * 4;

  __shared__ float ws[54];
  const int tid = threadIdx.y * 32 + tx;
  if (tid < 54) ws[tid] = W3[o * 54 + tid];
  __syncthreads();

  float acc[8][4];
#pragma unroll
  for (int i = 0; i < 8; i++) {
    acc[i][0] = 0.f; acc[i][1] = 0.f; acc[i][2] = 0.f; acc[i][3] = 0.f;
  }

#pragma unroll
  for (int ci = 0; ci < 2; ci++) {
    const float* basec = in + (size_t)((b * 112 + o * 2 + ci) * 8) * 16384;
#pragma unroll
    for (int dh = 0; dh < 3; dh++) {
      const int hh = h + dh - 1;
      if (hh < 0 || hh > 127) continue;
      float w9[3][3];
#pragma unroll
      for (int kd = 0; kd < 3; kd++)
#pragma unroll
        for (int dw = 0; dw < 3; dw++)
          w9[kd][dw] = ws[ci * 27 + kd * 9 + dh * 3 + dw];
      const float* rowp = basec + hh * 128 + w0;
#pragma unroll
      for (int d = 0; d < 8; d++) {
        const float* p = rowp + d * 16384;
        float4 m4 = *(const float4*)p;
        float vl = __shfl_up_sync(0xffffffffu, m4.w, 1);
        float vr = __shfl_down_sync(0xffffffffu, m4.x, 1);
        float v[6];
        v[0] = (tx == 0)  ? 0.f : vl;
        v[1] = m4.x; v[2] = m4.y; v[3] = m4.z; v[4] = m4.w;
        v[5] = (tx == 31) ? 0.f : vr;
#pragma unroll
        for (int kd = 0; kd < 3; kd++) {
          const int Bs = d + 1 - kd;
          if (Bs < 0 || Bs > 7) continue;
#pragma unroll
          for (int dw = 0; dw < 3; dw++) {
            const float wv = w9[kd][dw];
            acc[Bs][0] += wv * v[dw + 0];
            acc[Bs][1] += wv * v[dw + 1];
            acc[Bs][2] += wv * v[dw + 2];
            acc[Bs][3] += wv * v[dw + 3];
          }
        }
      }
    }
  }

  const int wy = h >> 3, ty = h & 7, wx = w0 >> 3, tx0 = w0 & 7;
  float* op = outw + (size_t)((((b * 16 + wy) * 16 + wx) * 56 + o) * 8) * 64
                   + ty * 8 + tx0;
#pragma unroll
  for (int Bs = 0; Bs < 8; Bs++) {
    *(float4*)(op + Bs * 64) =
        make_float4(acc[Bs][0], acc[Bs][1], acc[Bs][2], acc[Bs][3]);
  }
}

// ---------------------------------------------------------------------------
// Sigma kernel (per batch): Sq, Sk (permuted), theta for all 8 slices.
// t1_i = q_i.Kbar - m1_i*(q_i.k_i).  bid = bid_base + blockIdx.x.
// ---------------------------------------------------------------------------
__global__ __launch_bounds__(256) void sigma_kernel(
    const float* __restrict__ pcq_w, const float* __restrict__ pcq_b,
    const float* __restrict__ pck_w, const float* __restrict__ pck_b,
    const float* __restrict__ mlp1_w, const float* __restrict__ mlp2_w1,
    const float* __restrict__ mlp2_w2, int bid_base)
{
  __shared__ __align__(16) float m1[64], w2[64];
  __shared__ __align__(16) float kbar_s[128];    // [Bs][16]
  __shared__ __align__(16) float t1_all[512];    // [Bs][64]
  __shared__ __align__(16) float red2[512];
  __shared__ float pcqw[14], pckw[14];

  const int tid = threadIdx.x;
  const int bid = bid_base + blockIdx.x;    // win*4 + head
  const int head = bid & 3, win = bid >> 2;
  const int b = win >> 8, wy = (win >> 4) & 15, wx = win & 15;

  if (tid < 64) { m1[tid] = mlp1_w[tid]; w2[tid] = mlp2_w2[tid]; }
  if (tid < 14) { pcqw[tid] = pcq_w[tid]; pckw[tid] = pck_w[tid]; }
  const float bq = pcq_b[0], bk = pck_b[0];

  const size_t wbase = (size_t)((b * 16 + wy) * 16 + wx) * (56 * 8 * 64);
  const float* gqf = g_q + wbase + head * 14 * 512;
  const float* gkf = g_k + wbase + head * 14 * 512;
  const float4* gk = (const float4*)gkf;
  const float4* m14 = (const float4*)m1;
  const float4* t14 = (const float4*)t1_all;
  const float4* w14 = (const float4*)mlp2_w1;
  __syncthreads();

  // P1: Kbar[Bs][d]
#pragma unroll
  for (int rep = 0; rep < 2; rep++) {
    const int item = rep * 64 + (tid >> 2);
    const int p4 = tid & 3;
    if (item < 112) {
      const int Bs = item / 14, d = item % 14;
      float pr = 0.f;
#pragma unroll
      for (int c = 0; c < 4; c++) {
        float4 kv = gk[d * 128 + Bs * 16 + p4 * 4 + c];
        float4 mm = m14[p4 * 4 + c];
        pr += kv.x*mm.x + kv.y*mm.y + kv.z*mm.z + kv.w*mm.w;
      }
      pr += __shfl_xor_sync(0xffffffffu, pr, 1);
      pr += __shfl_xor_sync(0xffffffffu, pr, 2);
      if (p4 == 0) kbar_s[Bs * 16 + d] = pr;
    }
  }
  __syncthreads();

  // P2: per (Bs,i): Sq, Sk (permuted), t1
#pragma unroll
  for (int rep = 0; rep < 2; rep++) {
    const int t = tid + rep * 256;
    const int Bs = t >> 6, i = t & 63;
    float sq = bq, sk = bk, qkb = 0.f, dg = 0.f;
#pragma unroll
    for (int d = 0; d < 14; d++) {
      float qv = gqf[d * 512 + Bs * 64 + i];
      float kv = gkf[d * 512 + Bs * 64 + i];
      sq  += qv * pcqw[d];
      sk  += kv * pckw[d];
      qkb += qv * kbar_s[Bs * 16 + d];
      dg  += qv * kv;
    }
    g_sq[(size_t)bid * 512 + Bs * 64 + i] = sq;
    g_sk[(size_t)bid * 512 + Bs * 64 +
         ((((i >> 2) & 3) * 4 + (i >> 4)) * 4 + (i & 3))] = sk;
    t1_all[Bs * 64 + i] = qkb - m1[i] * dg;
  }
  __syncthreads();

  // P3: t2 = leaky(t1 @ w1^T); red2 = t2 * w2
#pragma unroll
  for (int rep = 0; rep < 2; rep++) {
    const int t = tid + rep * 256;
    const int Bs = t >> 6, o = t & 63;
    float s = 0.f;
#pragma unroll
    for (int c = 0; c < 16; c++) {
      float4 wv = __ldg(&w14[o * 16 + c]);
      float4 tv = t14[Bs * 16 + c];
      s += wv.x*tv.x + wv.y*tv.y + wv.z*tv.z + wv.w*tv.w;
    }
    s = (s > 0.f) ? s : 0.1f * s;
    red2[Bs * 64 + o] = s * w2[o];
  }
  __syncthreads();

  // P4: theta[Bs]
  {
    const int w = tid >> 5, lane = tid & 31;
    float s = red2[w * 64 + lane] + red2[w * 64 + lane + 32];
#pragma unroll
    for (int off = 16; off > 0; off >>= 1)
      s += __shfl_xor_sync(0xffffffffu, s, off);
    if (lane == 0) g_theta[bid * 8 + w] = s;
  }
}

// ---------------------------------------------------------------------------
// Slice attention: one block per (win, head, Bs). bid = bid_base + blockIdx.x.
// ---------------------------------------------------------------------------
__global__ __launch_bounds__(256, 4) void attn_slice_kernel(
    const float* __restrict__ Wout, float* __restrict__ out, int bid_base)
{
  __shared__ __align__(16) float q_s[896], k_s[896], v_s[896];
  __shared__ __align__(16) float sim[64 * 68];
  __shared__ __align__(16) float sks[64];
  __shared__ float woutc[28];
  __shared__ float theta_sh;

  const int tid = threadIdx.x;
  const int bid = bid_base + blockIdx.x;    // win*32 + head*8 + Bs
  const int Bs = bid & 7, head = (bid >> 3) & 3, win = bid >> 5;
  const int b = win >> 8, wy = (win >> 4) & 15, wx = win & 15;
  const int sidx = (bid >> 3) * 512 + Bs * 64;

  const size_t wbase = (size_t)((b * 16 + wy) * 16 + wx) * (56 * 8 * 64);
  const float4* gq = (const float4*)(g_q + wbase + head * 14 * 512);
  const float4* gk = (const float4*)(g_k + wbase + head * 14 * 512);
  const float4* gv = (const float4*)(g_v + wbase + head * 14 * 512);

  float4* q4 = (float4*)q_s; float4* k4 = (float4*)k_s; float4* v4 = (float4*)v_s;
  float4* sim4 = (float4*)sim;
  const float4* Sks4 = (const float4*)sks;

  const int irow = tid >> 2, p4 = tid & 3;
  const int it = tid >> 4, jt = tid & 15;
  const int hh = wy * 8 + (irow >> 3), ww = wx * 8 + (irow & 7);

  if (tid < 224) {
    int d = tid >> 4, t4 = tid & 15;
    int ga = d * 128 + Bs * 16 + t4;
    q4[d * 16 + t4] = gq[ga];
    k4[d * 16 + t4] = gk[ga];
    v4[d * 16 + (t4 & 3) * 4 + (t4 >> 2)] = gv[ga];
  } else {
    int t = tid - 224;
    if (t < 16) ((float4*)sks)[t] = ((const float4*)(g_sk + sidx))[t];
    if (t < 28) woutc[t] = Wout[head * 28 + t];
    if (t == 28) theta_sh = g_theta[bid];
  }
  __syncthreads();

  // sim = q^T k (4x4 register-tiled GEMM)
  {
    float a00=0,a01=0,a02=0,a03=0, a10=0,a11=0,a12=0,a13=0;
    float a20=0,a21=0,a22=0,a23=0, a30=0,a31=0,a32=0,a33=0;
#pragma unroll
    for (int d = 0; d < 14; d++) {
      float4 qv = q4[d * 16 + it];
      float4 kv = k4[d * 16 + jt];
      a00 += qv.x*kv.x; a01 += qv.x*kv.y; a02 += qv.x*kv.z; a03 += qv.x*kv.w;
      a10 += qv.y*kv.x; a11 += qv.y*kv.y; a12 += qv.y*kv.z; a13 += qv.y*kv.w;
      a20 += qv.z*kv.x; a21 += qv.z*kv.y; a22 += qv.z*kv.z; a23 += qv.z*kv.w;
      a30 += qv.w*kv.x; a31 += qv.w*kv.y; a32 += qv.w*kv.z; a33 += qv.w*kv.w;
    }
    const int rbase = it * 4;
    sim4[(rbase+0) * 17 + jt] = make_float4(a00,a01,a02,a03);
    sim4[(rbase+1) * 17 + jt] = make_float4(a10,a11,a12,a13);
    sim4[(rbase+2) * 17 + jt] = make_float4(a20,a21,a22,a23);
    sim4[(rbase+3) * 17 + jt] = make_float4(a30,a31,a32,a33);
  }
  __syncthreads();

  // scale, softmax, mask, out-GEMM, store
  {
    const float sq = g_sq[sidx + irow];
    const float th = theta_sh;
    float a[16];
    float m = -1e30f;
#pragma unroll
    for (int c = 0; c < 4; c++) {
      float4 sv = sim4[irow * 17 + p4 * 4 + c];
      float4 kv = Sks4[c * 4 + p4];
      a[c*4+0] = sv.x * sq * kv.x; a[c*4+1] = sv.y * sq * kv.y;
      a[c*4+2] = sv.z * sq * kv.z; a[c*4+3] = sv.w * sq * kv.w;
      m = fmaxf(m, fmaxf(fmaxf(a[c*4+0], a[c*4+1]), fmaxf(a[c*4+2], a[c*4+3])));
    }
    m = fmaxf(m, __shfl_xor_sync(0xffffffffu, m, 1));
    m = fmaxf(m, __shfl_xor_sync(0xffffffffu, m, 2));
    float sum = 0.f;
#pragma unroll
    for (int e = 0; e < 16; e++) {
      float xv = a[e];
      float ev = __expf(xv - m);
      sum += ev;
      a[e] = (xv > th) ? ev : 0.f;
    }
    sum += __shfl_xor_sync(0xffffffffu, sum, 1);
    sum += __shfl_xor_sync(0xffffffffu, sum, 2);
    const float r = 1.f / sum;
#pragma unroll
    for (int e = 0; e < 16; e++) a[e] *= r;

    const size_t sp = (size_t)Bs * 16384 + hh * 128 + ww;
    const size_t cb = (size_t)(b * 112 + head * 28) * 131072 + sp;
#pragma unroll
    for (int half = 0; half < 2; half++) {
      float oacc[7] = {0.f,0.f,0.f,0.f,0.f,0.f,0.f};
#pragma unroll
      for (int dd = 0; dd < 7; dd++) {
        const int d = half * 7 + dd;
#pragma unroll
        for (int c = 0; c < 4; c++) {
          float4 vv = v4[d * 16 + c * 4 + p4];
          oacc[dd] += a[c*4+0]*vv.x + a[c*4+1]*vv.y
                    + a[c*4+2]*vv.z + a[c*4+3]*vv.w;
        }
      }
#pragma unroll
      for (int dd = 0; dd < 7; dd++) {
        float s = oacc[dd];
        s += __shfl_xor_sync(0xffffffffu, s, 1);
        s += __shfl_xor_sync(0xffffffffu, s, 2);
        oacc[dd] = s;
      }
#pragma unroll
      for (int k = 0; k < 2; k++) {
        const int dd = p4 + 4 * k;
        if (dd < 7) {
          const int d = half * 7 + dd;
          out[cb + (size_t)(2 * d)     * 131072] = oacc[dd] * woutc[d * 2 + 0];
          out[cb + (size_t)(2 * d + 1) * 131072] = oacc[dd] * woutc[d * 2 + 1];
        }
      }
    }
  }
}

extern "C" void kernel_launch(void* const* d_in, const int* in_sizes, int n_in,
                              void* d_out, int out_size) {
  (void)in_sizes; (void)n_in; (void)out_size;
  const float* x      = (const float*)d_in[0];
  const float* last   = (const float*)d_in[1];
  const float* Wq     = (const float*)d_in[2];
  const float* Wk     = (const float*)d_in[3];
  const float* Wv     = (const float*)d_in[4];
  const float* Wout   = (const float*)d_in[5];
  const float* pcq_w  = (const float*)d_in[6];
  const float* pcq_b  = (const float*)d_in[7];
  const float* pck_w  = (const float*)d_in[8];
  const float* pck_b  = (const float*)d_in[9];
  const float* mlp1_w = (const float*)d_in[10];
  const float* mlp2w1 = (const float*)d_in[11];
  const float* mlp2w2 = (const float*)d_in[12];
  float* out = (float*)d_out;

  // lazily-created streams/events (resource init only; work is identical
  // every call and fully event-ordered -> deterministic, graph-capturable)
  static cudaStream_t s1 = 0, s2 = 0;
  static cudaEvent_t evF = 0, evC[2], evJ1 = 0, evJ2 = 0;
  if (s1 == 0) {
    cudaStreamCreateWithFlags(&s1, cudaStreamNonBlocking);
    cudaStreamCreateWithFlags(&s2, cudaStreamNonBlocking);
    cudaEventCreateWithFlags(&evF, cudaEventDisableTiming);
    for (int i = 0; i < 2; i++)
      cudaEventCreateWithFlags(&evC[i], cudaEventDisableTiming);
    cudaEventCreateWithFlags(&evJ1, cudaEventDisableTiming);
    cudaEventCreateWithFlags(&evJ2, cudaEventDisableTiming);
  }

  // fork from the caller's (captured) stream
  cudaEventRecord(evF, 0);
  cudaStreamWaitEvent(s1, evF, 0);
  cudaStreamWaitEvent(s2, evF, 0);

  // conv per-batch on s1 (full-size grids: 2688 blocks each)
  for (int b = 0; b < 2; b++) {
    conv_all_kernel<<<dim3(1, 16, 168), dim3(32, 8), 0, s1>>>(
        x, last, Wq, Wk, Wv, b);
    cudaEventRecord(evC[b], s1);
  }
  // sigma + attn per-batch on s2, each gated only on its conv batch
  for (int b = 0; b < 2; b++) {
    cudaStreamWaitEvent(s2, evC[b], 0);
    sigma_kernel<<<1024, 256, 0, s2>>>(pcq_w, pcq_b, pck_w, pck_b,
                                       mlp1_w, mlp2w1, mlp2w2, b * 1024);
    attn_slice_kernel<<<8192, 256, 0, s2>>>(Wout, out, b * 8192);
  }

  // join back to the caller's stream
  cudaEventRecord(evJ1, s1);
  cudaEventRecord(evJ2, s2);
  cudaStreamWaitEvent(0, evJ1, 0);
  cudaStreamWaitEvent(0, evJ2, 0);
}

// round 12
// speedup vs baseline: 1.1138x; 1.0283x over previous
#include <cuda_runtime.h>

// qkv scratch in windowed layout: [b(2)][wy(16)][wx(16)][ch(56)][Bs(8)][tok(64)]
#define NELEM_QKV (2*16*16*56*8*64)
__device__ float g_q[NELEM_QKV];
__device__ float g_k[NELEM_QKV];
__device__ float g_v[NELEM_QKV];
// sigma scratch: [win*4+head][Bs][64] (Sk stored PERMUTED), theta: [sbid*8+Bs]
__device__ float g_sq[2048 * 512];
__device__ float g_sk[2048 * 512];
__device__ float g_theta[16384];

// ---------------------------------------------------------------------------
// All three grouped 3x3x3 convs, one launch (measured best: 128.3 us).
// z<112: q from x. z>=112: k/v from last interleaved (L2 reuse).
// ---------------------------------------------------------------------------
__global__ __launch_bounds__(256) void conv_all_kernel(
    const float* __restrict__ x, const float* __restrict__ last,
    const float* __restrict__ Wq, const float* __restrict__ Wk,
    const float* __restrict__ Wv)
{
  const int z = blockIdx.z;
  int idx, sel;
  if (z < 112) { idx = z; sel = 0; }
  else { int zz = z - 112; idx = zz >> 1; sel = 1 + (zz & 1); }
  const float* in = (sel == 0) ? x : last;
  const float* W3 = (sel == 0) ? Wq : (sel == 1) ? Wk : Wv;
  float* outw     = (sel == 0) ? g_q : (sel == 1) ? g_k : g_v;

  const int b = idx / 56, o = idx % 56;
  const int h = blockIdx.y * 8 + threadIdx.y;
  const int tx = threadIdx.x;
  const int w0 = tx * 4;

  __shared__ float ws[54];
  const int tid = threadIdx.y * 32 + tx;
  if (tid < 54) ws[tid] = W3[o * 54 + tid];
  __syncthreads();

  float acc[8][4];
#pragma unroll
  for (int i = 0; i < 8; i++) {
    acc[i][0] = 0.f; acc[i][1] = 0.f; acc[i][2] = 0.f; acc[i][3] = 0.f;
  }

#pragma unroll
  for (int ci = 0; ci < 2; ci++) {
    const float* basec = in + (size_t)((b * 112 + o * 2 + ci) * 8) * 16384;
#pragma unroll
    for (int dh = 0; dh < 3; dh++) {
      const int hh = h + dh - 1;
      if (hh < 0 || hh > 127) continue;
      float w9[3][3];
#pragma unroll
      for (int kd = 0; kd < 3; kd++)
#pragma unroll
        for (int dw = 0; dw < 3; dw++)
          w9[kd][dw] = ws[ci * 27 + kd * 9 + dh * 3 + dw];
      const float* rowp = basec + hh * 128 + w0;
#pragma unroll
      for (int d = 0; d < 8; d++) {
        const float* p = rowp + d * 16384;
        float4 m4 = *(const float4*)p;
        float vl = __shfl_up_sync(0xffffffffu, m4.w, 1);
        float vr = __shfl_down_sync(0xffffffffu, m4.x, 1);
        float v[6];
        v[0] = (tx == 0)  ? 0.f : vl;
        v[1] = m4.x; v[2] = m4.y; v[3] = m4.z; v[4] = m4.w;
        v[5] = (tx == 31) ? 0.f : vr;
#pragma unroll
        for (int kd = 0; kd < 3; kd++) {
          const int Bs = d + 1 - kd;
          if (Bs < 0 || Bs > 7) continue;
#pragma unroll
          for (int dw = 0; dw < 3; dw++) {
            const float wv = w9[kd][dw];
            acc[Bs][0] += wv * v[dw + 0];
            acc[Bs][1] += wv * v[dw + 1];
            acc[Bs][2] += wv * v[dw + 2];
            acc[Bs][3] += wv * v[dw + 3];
          }
        }
      }
    }
  }

  const int wy = h >> 3, ty = h & 7, wx = w0 >> 3, tx0 = w0 & 7;
  float* op = outw + (size_t)((((b * 16 + wy) * 16 + wx) * 56 + o) * 8) * 64
                   + ty * 8 + tx0;
#pragma unroll
  for (int Bs = 0; Bs < 8; Bs++) {
    *(float4*)(op + Bs * 64) =
        make_float4(acc[Bs][0], acc[Bs][1], acc[Bs][2], acc[Bs][3]);
  }
}

// ---------------------------------------------------------------------------
// Sigma kernel: Sq, Sk (permuted), theta for all 8 slices.
// t1_i = q_i.Kbar - m1_i*(q_i.k_i).
// ---------------------------------------------------------------------------
__global__ __launch_bounds__(256) void sigma_kernel(
    const float* __restrict__ pcq_w, const float* __restrict__ pcq_b,
    const float* __restrict__ pck_w, const float* __restrict__ pck_b,
    const float* __restrict__ mlp1_w, const float* __restrict__ mlp2_w1,
    const float* __restrict__ mlp2_w2)
{
  __shared__ __align__(16) float m1[64], w2[64];
  __shared__ __align__(16) float kbar_s[128];    // [Bs][16]
  __shared__ __align__(16) float t1_all[512];    // [Bs][64]
  __shared__ __align__(16) float red2[512];
  __shared__ float pcqw[14], pckw[14];

  const int tid = threadIdx.x;
  const int bid = blockIdx.x;               // win*4 + head
  const int head = bid & 3, win = bid >> 2;
  const int b = win >> 8, wy = (win >> 4) & 15, wx = win & 15;

  if (tid < 64) { m1[tid] = mlp1_w[tid]; w2[tid] = mlp2_w2[tid]; }
  if (tid < 14) { pcqw[tid] = pcq_w[tid]; pckw[tid] = pck_w[tid]; }
  const float bq = pcq_b[0], bk = pck_b[0];

  const size_t wbase = (size_t)((b * 16 + wy) * 16 + wx) * (56 * 8 * 64);
  const float* gqf = g_q + wbase + head * 14 * 512;
  const float* gkf = g_k + wbase + head * 14 * 512;
  const float4* gk = (const float4*)gkf;
  const float4* m14 = (const float4*)m1;
  const float4* t14 = (const float4*)t1_all;
  const float4* w14 = (const float4*)mlp2_w1;
  __syncthreads();

  // P1: Kbar[Bs][d]
#pragma unroll
  for (int rep = 0; rep < 2; rep++) {
    const int item = rep * 64 + (tid >> 2);
    const int p4 = tid & 3;
    if (item < 112) {
      const int Bs = item / 14, d = item % 14;
      float pr = 0.f;
#pragma unroll
      for (int c = 0; c < 4; c++) {
        float4 kv = gk[d * 128 + Bs * 16 + p4 * 4 + c];
        float4 mm = m14[p4 * 4 + c];
        pr += kv.x*mm.x + kv.y*mm.y + kv.z*mm.z + kv.w*mm.w;
      }
      pr += __shfl_xor_sync(0xffffffffu, pr, 1);
      pr += __shfl_xor_sync(0xffffffffu, pr, 2);
      if (p4 == 0) kbar_s[Bs * 16 + d] = pr;
    }
  }
  __syncthreads();

  // P2: per (Bs,i): Sq, Sk (permuted), t1
#pragma unroll
  for (int rep = 0; rep < 2; rep++) {
    const int t = tid + rep * 256;
    const int Bs = t >> 6, i = t & 63;
    float sq = bq, sk = bk, qkb = 0.f, dg = 0.f;
#pragma unroll
    for (int d = 0; d < 14; d++) {
      float qv = gqf[d * 512 + Bs * 64 + i];
      float kv = gkf[d * 512 + Bs * 64 + i];
      sq  += qv * pcqw[d];
      sk  += kv * pckw[d];
      qkb += qv * kbar_s[Bs * 16 + d];
      dg  += qv * kv;
    }
    g_sq[(size_t)bid * 512 + Bs * 64 + i] = sq;
    g_sk[(size_t)bid * 512 + Bs * 64 +
         ((((i >> 2) & 3) * 4 + (i >> 4)) * 4 + (i & 3))] = sk;
    t1_all[Bs * 64 + i] = qkb - m1[i] * dg;
  }
  __syncthreads();

  // P3: t2 = leaky(t1 @ w1^T); red2 = t2 * w2
#pragma unroll
  for (int rep = 0; rep < 2; rep++) {
    const int t = tid + rep * 256;
    const int Bs = t >> 6, o = t & 63;
    float s = 0.f;
#pragma unroll
    for (int c = 0; c < 16; c++) {
      float4 wv = __ldg(&w14[o * 16 + c]);
      float4 tv = t14[Bs * 16 + c];
      s += wv.x*tv.x + wv.y*tv.y + wv.z*tv.z + wv.w*tv.w;
    }
    s = (s > 0.f) ? s : 0.1f * s;
    red2[Bs * 64 + o] = s * w2[o];
  }
  __syncthreads();

  // P4: theta[Bs]
  {
    const int w = tid >> 5, lane = tid & 31;
    float s = red2[w * 64 + lane] + red2[w * 64 + lane + 32];
#pragma unroll
    for (int off = 16; off > 0; off >>= 1)
      s += __shfl_xor_sync(0xffffffffu, s, off);
    if (lane == 0) g_theta[bid * 8 + w] = s;
  }
}

// ---------------------------------------------------------------------------
// Slice attention: one block per (win, head, Bs). bid = bid_base + blockIdx.x.
// ---------------------------------------------------------------------------
__global__ __launch_bounds__(256, 4) void attn_slice_kernel(
    const float* __restrict__ Wout, float* __restrict__ out, int bid_base)
{
  __shared__ __align__(16) float q_s[896], k_s[896], v_s[896];
  __shared__ __align__(16) float sim[64 * 68];
  __shared__ __align__(16) float sks[64];
  __shared__ float woutc[28];
  __shared__ float theta_sh;

  const int tid = threadIdx.x;
  const int bid = bid_base + blockIdx.x;    // win*32 + head*8 + Bs
  const int Bs = bid & 7, head = (bid >> 3) & 3, win = bid >> 5;
  const int b = win >> 8, wy = (win >> 4) & 15, wx = win & 15;
  const int sidx = (bid >> 3) * 512 + Bs * 64;

  const size_t wbase = (size_t)((b * 16 + wy) * 16 + wx) * (56 * 8 * 64);
  const float4* gq = (const float4*)(g_q + wbase + head * 14 * 512);
  const float4* gk = (const float4*)(g_k + wbase + head * 14 * 512);
  const float4* gv = (const float4*)(g_v + wbase + head * 14 * 512);

  float4* q4 = (float4*)q_s; float4* k4 = (float4*)k_s; float4* v4 = (float4*)v_s;
  float4* sim4 = (float4*)sim;
  const float4* Sks4 = (const float4*)sks;

  const int irow = tid >> 2, p4 = tid & 3;
  const int it = tid >> 4, jt = tid & 15;
  const int hh = wy * 8 + (irow >> 3), ww = wx * 8 + (irow & 7);

  if (tid < 224) {
    int d = tid >> 4, t4 = tid & 15;
    int ga = d * 128 + Bs * 16 + t4;
    q4[d * 16 + t4] = gq[ga];
    k4[d * 16 + t4] = gk[ga];
    v4[d * 16 + (t4 & 3) * 4 + (t4 >> 2)] = gv[ga];
  } else {
    int t = tid - 224;
    if (t < 16) ((float4*)sks)[t] = ((const float4*)(g_sk + sidx))[t];
    if (t < 28) woutc[t] = Wout[head * 28 + t];
    if (t == 28) theta_sh = g_theta[bid];
  }
  __syncthreads();

  // sim = q^T k (4x4 register-tiled GEMM)
  {
    float a00=0,a01=0,a02=0,a03=0, a10=0,a11=0,a12=0,a13=0;
    float a20=0,a21=0,a22=0,a23=0, a30=0,a31=0,a32=0,a33=0;
#pragma unroll
    for (int d = 0; d < 14; d++) {
      float4 qv = q4[d * 16 + it];
      float4 kv = k4[d * 16 + jt];
      a00 += qv.x*kv.x; a01 += qv.x*kv.y; a02 += qv.x*kv.z; a03 += qv.x*kv.w;
      a10 += qv.y*kv.x; a11 += qv.y*kv.y; a12 += qv.y*kv.z; a13 += qv.y*kv.w;
      a20 += qv.z*kv.x; a21 += qv.z*kv.y; a22 += qv.z*kv.z; a23 += qv.z*kv.w;
      a30 += qv.w*kv.x; a31 += qv.w*kv.y; a32 += qv.w*kv.z; a33 += qv.w*kv.w;
    }
    const int rbase = it * 4;
    sim4[(rbase+0) * 17 + jt] = make_float4(a00,a01,a02,a03);
    sim4[(rbase+1) * 17 + jt] = make_float4(a10,a11,a12,a13);
    sim4[(rbase+2) * 17 + jt] = make_float4(a20,a21,a22,a23);
    sim4[(rbase+3) * 17 + jt] = make_float4(a30,a31,a32,a33);
  }
  __syncthreads();

  // scale, softmax, mask, out-GEMM, store
  {
    const float sq = g_sq[sidx + irow];
    const float th = theta_sh;
    float a[16];
    float m = -1e30f;
#pragma unroll
    for (int c = 0; c < 4; c++) {
      float4 sv = sim4[irow * 17 + p4 * 4 + c];
      float4 kv = Sks4[c * 4 + p4];
      a[c*4+0] = sv.x * sq * kv.x; a[c*4+1] = sv.y * sq * kv.y;
      a[c*4+2] = sv.z * sq * kv.z; a[c*4+3] = sv.w * sq * kv.w;
      m = fmaxf(m, fmaxf(fmaxf(a[c*4+0], a[c*4+1]), fmaxf(a[c*4+2], a[c*4+3])));
    }
    m = fmaxf(m, __shfl_xor_sync(0xffffffffu, m, 1));
    m = fmaxf(m, __shfl_xor_sync(0xffffffffu, m, 2));
    float sum = 0.f;
#pragma unroll
    for (int e = 0; e < 16; e++) {
      float xv = a[e];
      float ev = __expf(xv - m);
      sum += ev;
      a[e] = (xv > th) ? ev : 0.f;
    }
    sum += __shfl_xor_sync(0xffffffffu, sum, 1);
    sum += __shfl_xor_sync(0xffffffffu, sum, 2);
    const float r = 1.f / sum;
#pragma unroll
    for (int e = 0; e < 16; e++) a[e] *= r;

    const size_t sp = (size_t)Bs * 16384 + hh * 128 + ww;
    const size_t cb = (size_t)(b * 112 + head * 28) * 131072 + sp;
#pragma unroll
    for (int half = 0; half < 2; half++) {
      float oacc[7] = {0.f,0.f,0.f,0.f,0.f,0.f,0.f};
#pragma unroll
      for (int dd = 0; dd < 7; dd++) {
        const int d = half * 7 + dd;
#pragma unroll
        for (int c = 0; c < 4; c++) {
          float4 vv = v4[d * 16 + c * 4 + p4];
          oacc[dd] += a[c*4+0]*vv.x + a[c*4+1]*vv.y
                    + a[c*4+2]*vv.z + a[c*4+3]*vv.w;
        }
      }
#pragma unroll
      for (int dd = 0; dd < 7; dd++) {
        float s = oacc[dd];
        s += __shfl_xor_sync(0xffffffffu, s, 1);
        s += __shfl_xor_sync(0xffffffffu, s, 2);
        oacc[dd] = s;
      }
#pragma unroll
      for (int k = 0; k < 2; k++) {
        const int dd = p4 + 4 * k;
        if (dd < 7) {
          const int d = half * 7 + dd;
          out[cb + (size_t)(2 * d)     * 131072] = oacc[dd] * woutc[d * 2 + 0];
          out[cb + (size_t)(2 * d + 1) * 131072] = oacc[dd] * woutc[d * 2 + 1];
        }
      }
    }
  }
}

extern "C" void kernel_launch(void* const* d_in, const int* in_sizes, int n_in,
                              void* d_out, int out_size) {
  (void)in_sizes; (void)n_in; (void)out_size;
  const float* x      = (const float*)d_in[0];
  const float* last   = (const float*)d_in[1];
  const float* Wq     = (const float*)d_in[2];
  const float* Wk     = (const float*)d_in[3];
  const float* Wv     = (const float*)d_in[4];
  const float* Wout   = (const float*)d_in[5];
  const float* pcq_w  = (const float*)d_in[6];
  const float* pcq_b  = (const float*)d_in[7];
  const float* pck_w  = (const float*)d_in[8];
  const float* pck_b  = (const float*)d_in[9];
  const float* mlp1_w = (const float*)d_in[10];
  const float* mlp2w1 = (const float*)d_in[11];
  const float* mlp2w2 = (const float*)d_in[12];
  float* out = (float*)d_out;

  // Serial, single stream — assembled from each phase's measured-best config.
  conv_all_kernel<<<dim3(1, 16, 336), dim3(32, 8)>>>(x, last, Wq, Wk, Wv);
  sigma_kernel<<<2048, 256>>>(pcq_w, pcq_b, pck_w, pck_b,
                              mlp1_w, mlp2w1, mlp2w2);
  attn_slice_kernel<<<8192, 256>>>(Wout, out, 0);
  attn_slice_kernel<<<8192, 256>>>(Wout, out, 8192);
}

// round 13
// speedup vs baseline: 1.1191x; 1.0047x over previous
#include <cuda_runtime.h>

// qkv scratch in windowed layout: [b(2)][wy(16)][wx(16)][ch(56)][Bs(8)][tok(64)]
#define NELEM_QKV (2*16*16*56*8*64)
__device__ float g_q[NELEM_QKV];
__device__ float g_k[NELEM_QKV];
__device__ float g_v[NELEM_QKV];
// sigma scratch: [win*4+head][Bs][64] (Sk stored PERMUTED), theta: [sbid*8+Bs]
__device__ float g_sq[2048 * 512];
__device__ float g_sk[2048 * 512];
__device__ float g_theta[16384];

// ---------------------------------------------------------------------------
// All three grouped 3x3x3 convs, one launch (measured at the FFMA-rate floor).
// ---------------------------------------------------------------------------
__global__ __launch_bounds__(256) void conv_all_kernel(
    const float* __restrict__ x, const float* __restrict__ last,
    const float* __restrict__ Wq, const float* __restrict__ Wk,
    const float* __restrict__ Wv)
{
  const int z = blockIdx.z;
  int idx, sel;
  if (z < 112) { idx = z; sel = 0; }
  else { int zz = z - 112; idx = zz >> 1; sel = 1 + (zz & 1); }
  const float* in = (sel == 0) ? x : last;
  const float* W3 = (sel == 0) ? Wq : (sel == 1) ? Wk : Wv;
  float* outw     = (sel == 0) ? g_q : (sel == 1) ? g_k : g_v;

  const int b = idx / 56, o = idx % 56;
  const int h = blockIdx.y * 8 + threadIdx.y;
  const int tx = threadIdx.x;
  const int w0 = tx * 4;

  __shared__ float ws[54];
  const int tid = threadIdx.y * 32 + tx;
  if (tid < 54) ws[tid] = W3[o * 54 + tid];
  __syncthreads();

  float acc[8][4];
#pragma unroll
  for (int i = 0; i < 8; i++) {
    acc[i][0] = 0.f; acc[i][1] = 0.f; acc[i][2] = 0.f; acc[i][3] = 0.f;
  }

#pragma unroll
  for (int ci = 0; ci < 2; ci++) {
    const float* basec = in + (size_t)((b * 112 + o * 2 + ci) * 8) * 16384;
#pragma unroll
    for (int dh = 0; dh < 3; dh++) {
      const int hh = h + dh - 1;
      if (hh < 0 || hh > 127) continue;
      float w9[3][3];
#pragma unroll
      for (int kd = 0; kd < 3; kd++)
#pragma unroll
        for (int dw = 0; dw < 3; dw++)
          w9[kd][dw] = ws[ci * 27 + kd * 9 + dh * 3 + dw];
      const float* rowp = basec + hh * 128 + w0;
#pragma unroll
      for (int d = 0; d < 8; d++) {
        const float* p = rowp + d * 16384;
        float4 m4 = *(const float4*)p;
        float vl = __shfl_up_sync(0xffffffffu, m4.w, 1);
        float vr = __shfl_down_sync(0xffffffffu, m4.x, 1);
        float v[6];
        v[0] = (tx == 0)  ? 0.f : vl;
        v[1] = m4.x; v[2] = m4.y; v[3] = m4.z; v[4] = m4.w;
        v[5] = (tx == 31) ? 0.f : vr;
#pragma unroll
        for (int kd = 0; kd < 3; kd++) {
          const int Bs = d + 1 - kd;
          if (Bs < 0 || Bs > 7) continue;
#pragma unroll
          for (int dw = 0; dw < 3; dw++) {
            const float wv = w9[kd][dw];
            acc[Bs][0] += wv * v[dw + 0];
            acc[Bs][1] += wv * v[dw + 1];
            acc[Bs][2] += wv * v[dw + 2];
            acc[Bs][3] += wv * v[dw + 3];
          }
        }
      }
    }
  }

  const int wy = h >> 3, ty = h & 7, wx = w0 >> 3, tx0 = w0 & 7;
  float* op = outw + (size_t)((((b * 16 + wy) * 16 + wx) * 56 + o) * 8) * 64
                   + ty * 8 + tx0;
#pragma unroll
  for (int Bs = 0; Bs < 8; Bs++) {
    *(float4*)(op + Bs * 64) =
        make_float4(acc[Bs][0], acc[Bs][1], acc[Bs][2], acc[Bs][3]);
  }
}

// ---------------------------------------------------------------------------
// Sigma kernel: Sq, Sk (permuted), theta for all 8 slices.
// t1_i = q_i.Kbar - m1_i*(q_i.k_i).
// ---------------------------------------------------------------------------
__global__ __launch_bounds__(256) void sigma_kernel(
    const float* __restrict__ pcq_w, const float* __restrict__ pcq_b,
    const float* __restrict__ pck_w, const float* __restrict__ pck_b,
    const float* __restrict__ mlp1_w, const float* __restrict__ mlp2_w1,
    const float* __restrict__ mlp2_w2)
{
  __shared__ __align__(16) float m1[64], w2[64];
  __shared__ __align__(16) float kbar_s[128];    // [Bs][16]
  __shared__ __align__(16) float t1_all[512];    // [Bs][64]
  __shared__ __align__(16) float red2[512];
  __shared__ float pcqw[14], pckw[14];

  const int tid = threadIdx.x;
  const int bid = blockIdx.x;               // win*4 + head
  const int head = bid & 3, win = bid >> 2;
  const int b = win >> 8, wy = (win >> 4) & 15, wx = win & 15;

  if (tid < 64) { m1[tid] = mlp1_w[tid]; w2[tid] = mlp2_w2[tid]; }
  if (tid < 14) { pcqw[tid] = pcq_w[tid]; pckw[tid] = pck_w[tid]; }
  const float bq = pcq_b[0], bk = pck_b[0];

  const size_t wbase = (size_t)((b * 16 + wy) * 16 + wx) * (56 * 8 * 64);
  const float* gqf = g_q + wbase + head * 14 * 512;
  const float* gkf = g_k + wbase + head * 14 * 512;
  const float4* gk = (const float4*)gkf;
  const float4* m14 = (const float4*)m1;
  const float4* t14 = (const float4*)t1_all;
  const float4* w14 = (const float4*)mlp2_w1;
  __syncthreads();

  // P1: Kbar[Bs][d]
#pragma unroll
  for (int rep = 0; rep < 2; rep++) {
    const int item = rep * 64 + (tid >> 2);
    const int p4 = tid & 3;
    if (item < 112) {
      const int Bs = item / 14, d = item % 14;
      float pr = 0.f;
#pragma unroll
      for (int c = 0; c < 4; c++) {
        float4 kv = gk[d * 128 + Bs * 16 + p4 * 4 + c];
        float4 mm = m14[p4 * 4 + c];
        pr += kv.x*mm.x + kv.y*mm.y + kv.z*mm.z + kv.w*mm.w;
      }
      pr += __shfl_xor_sync(0xffffffffu, pr, 1);
      pr += __shfl_xor_sync(0xffffffffu, pr, 2);
      if (p4 == 0) kbar_s[Bs * 16 + d] = pr;
    }
  }
  __syncthreads();

  // P2: per (Bs,i): Sq, Sk (permuted), t1
#pragma unroll
  for (int rep = 0; rep < 2; rep++) {
    const int t = tid + rep * 256;
    const int Bs = t >> 6, i = t & 63;
    float sq = bq, sk = bk, qkb = 0.f, dg = 0.f;
#pragma unroll
    for (int d = 0; d < 14; d++) {
      float qv = gqf[d * 512 + Bs * 64 + i];
      float kv = gkf[d * 512 + Bs * 64 + i];
      sq  += qv * pcqw[d];
      sk  += kv * pckw[d];
      qkb += qv * kbar_s[Bs * 16 + d];
      dg  += qv * kv;
    }
    g_sq[(size_t)bid * 512 + Bs * 64 + i] = sq;
    g_sk[(size_t)bid * 512 + Bs * 64 +
         ((((i >> 2) & 3) * 4 + (i >> 4)) * 4 + (i & 3))] = sk;
    t1_all[Bs * 64 + i] = qkb - m1[i] * dg;
  }
  __syncthreads();

  // P3: t2 = leaky(t1 @ w1^T); red2 = t2 * w2
#pragma unroll
  for (int rep = 0; rep < 2; rep++) {
    const int t = tid + rep * 256;
    const int Bs = t >> 6, o = t & 63;
    float s = 0.f;
#pragma unroll
    for (int c = 0; c < 16; c++) {
      float4 wv = __ldg(&w14[o * 16 + c]);
      float4 tv = t14[Bs * 16 + c];
      s += wv.x*tv.x + wv.y*tv.y + wv.z*tv.z + wv.w*tv.w;
    }
    s = (s > 0.f) ? s : 0.1f * s;
    red2[Bs * 64 + o] = s * w2[o];
  }
  __syncthreads();

  // P4: theta[Bs]
  {
    const int w = tid >> 5, lane = tid & 31;
    float s = red2[w * 64 + lane] + red2[w * 64 + lane + 32];
#pragma unroll
    for (int off = 16; off > 0; off >>= 1)
      s += __shfl_xor_sync(0xffffffffu, s, off);
    if (lane == 0) g_theta[bid * 8 + w] = s;
  }
}

// ---------------------------------------------------------------------------
// Slice attention: one block per (win, head, Bs) = 16384 blocks.
// C phase uses a 16i x 32j warp tile so every k-load is a full 128B wavefront.
// ---------------------------------------------------------------------------
__global__ __launch_bounds__(256, 4) void attn_slice_kernel(
    const float* __restrict__ Wout, float* __restrict__ out)
{
  __shared__ __align__(16) float q_s[896], k_s[896], v_s[896];
  __shared__ __align__(16) float sim[64 * 68];
  __shared__ __align__(16) float sks[64];
  __shared__ float woutc[28];
  __shared__ float theta_sh;

  const int tid = threadIdx.x;
  const int bid = blockIdx.x;               // win*32 + head*8 + Bs
  const int Bs = bid & 7, head = (bid >> 3) & 3, win = bid >> 5;
  const int b = win >> 8, wy = (win >> 4) & 15, wx = win & 15;
  const int sidx = (bid >> 3) * 512 + Bs * 64;

  const size_t wbase = (size_t)((b * 16 + wy) * 16 + wx) * (56 * 8 * 64);
  const float4* gq = (const float4*)(g_q + wbase + head * 14 * 512);
  const float4* gk = (const float4*)(g_k + wbase + head * 14 * 512);
  const float4* gv = (const float4*)(g_v + wbase + head * 14 * 512);

  float4* q4 = (float4*)q_s; float4* k4 = (float4*)k_s; float4* v4 = (float4*)v_s;
  float4* sim4 = (float4*)sim;
  const float4* Sks4 = (const float4*)sks;

  const int irow = tid >> 2, p4 = tid & 3;      // FG quad ownership
  // C-phase 16i x 32j warp tile
  const int wi = (tid >> 5) & 3, wj = tid >> 7; // warp i-block / j-half
  const int lane = tid & 31;
  const int it2 = lane >> 3, jt2 = lane & 7;    // 4 i-quads x 8 j-quads
  const int hh = wy * 8 + (irow >> 3), ww = wx * 8 + (irow & 7);

  if (tid < 224) {
    int d = tid >> 4, t4 = tid & 15;
    int ga = d * 128 + Bs * 16 + t4;
    q4[d * 16 + t4] = gq[ga];
    k4[d * 16 + t4] = gk[ga];
    v4[d * 16 + (t4 & 3) * 4 + (t4 >> 2)] = gv[ga];
  } else {
    int t = tid - 224;
    if (t < 16) ((float4*)sks)[t] = ((const float4*)(g_sk + sidx))[t];
    if (t < 28) woutc[t] = Wout[head * 28 + t];
    if (t == 28) theta_sh = g_theta[bid];
  }
  __syncthreads();

  // sim = q^T k: warp tile 16i x 32j, thread tile 4x4.
  // q-load: 4 distinct float4/warp (64B, 1 wf); k-load: 8 distinct (128B, 1 wf)
  {
    const int iq = wi * 4 + it2;        // i-quad index (0..15)
    const int cq = wj * 8 + jt2;        // j-quad index (0..15)
    float a00=0,a01=0,a02=0,a03=0, a10=0,a11=0,a12=0,a13=0;
    float a20=0,a21=0,a22=0,a23=0, a30=0,a31=0,a32=0,a33=0;
#pragma unroll
    for (int d = 0; d < 14; d++) {
      float4 qv = q4[d * 16 + iq];
      float4 kv = k4[d * 16 + cq];
      a00 += qv.x*kv.x; a01 += qv.x*kv.y; a02 += qv.x*kv.z; a03 += qv.x*kv.w;
      a10 += qv.y*kv.x; a11 += qv.y*kv.y; a12 += qv.y*kv.z; a13 += qv.y*kv.w;
      a20 += qv.z*kv.x; a21 += qv.z*kv.y; a22 += qv.z*kv.z; a23 += qv.z*kv.w;
      a30 += qv.w*kv.x; a31 += qv.w*kv.y; a32 += qv.w*kv.z; a33 += qv.w*kv.w;
    }
    const int rbase = iq * 4;
    sim4[(rbase+0) * 17 + cq] = make_float4(a00,a01,a02,a03);
    sim4[(rbase+1) * 17 + cq] = make_float4(a10,a11,a12,a13);
    sim4[(rbase+2) * 17 + cq] = make_float4(a20,a21,a22,a23);
    sim4[(rbase+3) * 17 + cq] = make_float4(a30,a31,a32,a33);
  }
  __syncthreads();

  // scale, softmax, mask, out-GEMM, store
  {
    const float sq = g_sq[sidx + irow];
    const float th = theta_sh;
    float a[16];
    float m = -1e30f;
#pragma unroll
    for (int c = 0; c < 4; c++) {
      float4 sv = sim4[irow * 17 + p4 * 4 + c];
      float4 kv = Sks4[c * 4 + p4];
      a[c*4+0] = sv.x * sq * kv.x; a[c*4+1] = sv.y * sq * kv.y;
      a[c*4+2] = sv.z * sq * kv.z; a[c*4+3] = sv.w * sq * kv.w;
      m = fmaxf(m, fmaxf(fmaxf(a[c*4+0], a[c*4+1]), fmaxf(a[c*4+2], a[c*4+3])));
    }
    m = fmaxf(m, __shfl_xor_sync(0xffffffffu, m, 1));
    m = fmaxf(m, __shfl_xor_sync(0xffffffffu, m, 2));
    float sum = 0.f;
#pragma unroll
    for (int e = 0; e < 16; e++) {
      float xv = a[e];
      float ev = __expf(xv - m);
      sum += ev;
      a[e] = (xv > th) ? ev : 0.f;
    }
    sum += __shfl_xor_sync(0xffffffffu, sum, 1);
    sum += __shfl_xor_sync(0xffffffffu, sum, 2);
    const float r = 1.f / sum;
#pragma unroll
    for (int e = 0; e < 16; e++) a[e] *= r;

    const size_t sp = (size_t)Bs * 16384 + hh * 128 + ww;
    const size_t cb = (size_t)(b * 112 + head * 28) * 131072 + sp;
#pragma unroll
    for (int half = 0; half < 2; half++) {
      float oacc[7] = {0.f,0.f,0.f,0.f,0.f,0.f,0.f};
#pragma unroll
      for (int dd = 0; dd < 7; dd++) {
        const int d = half * 7 + dd;
#pragma unroll
        for (int c = 0; c < 4; c++) {
          float4 vv = v4[d * 16 + c * 4 + p4];
          oacc[dd] += a[c*4+0]*vv.x + a[c*4+1]*vv.y
                    + a[c*4+2]*vv.z + a[c*4+3]*vv.w;
        }
      }
#pragma unroll
      for (int dd = 0; dd < 7; dd++) {
        float s = oacc[dd];
        s += __shfl_xor_sync(0xffffffffu, s, 1);
        s += __shfl_xor_sync(0xffffffffu, s, 2);
        oacc[dd] = s;
      }
#pragma unroll
      for (int k = 0; k < 2; k++) {
        const int dd = p4 + 4 * k;
        if (dd < 7) {
          const int d = half * 7 + dd;
          out[cb + (size_t)(2 * d)     * 131072] = oacc[dd] * woutc[d * 2 + 0];
          out[cb + (size_t)(2 * d + 1) * 131072] = oacc[dd] * woutc[d * 2 + 1];
        }
      }
    }
  }
}

extern "C" void kernel_launch(void* const* d_in, const int* in_sizes, int n_in,
                              void* d_out, int out_size) {
  (void)in_sizes; (void)n_in; (void)out_size;
  const float* x      = (const float*)d_in[0];
  const float* last   = (const float*)d_in[1];
  const float* Wq     = (const float*)d_in[2];
  const float* Wk     = (const float*)d_in[3];
  const float* Wv     = (const float*)d_in[4];
  const float* Wout   = (const float*)d_in[5];
  const float* pcq_w  = (const float*)d_in[6];
  const float* pcq_b  = (const float*)d_in[7];
  const float* pck_w  = (const float*)d_in[8];
  const float* pck_b  = (const float*)d_in[9];
  const float* mlp1_w = (const float*)d_in[10];
  const float* mlp2w1 = (const float*)d_in[11];
  const float* mlp2w2 = (const float*)d_in[12];
  float* out = (float*)d_out;

  conv_all_kernel<<<dim3(1, 16, 336), dim3(32, 8)>>>(x, last, Wq, Wk, Wv);
  sigma_kernel<<<2048, 256>>>(pcq_w, pcq_b, pck_w, pck_b,
                              mlp1_w, mlp2w1, mlp2w2);
  attn_slice_kernel<<<16384, 256>>>(Wout, out);
}